// round 7
// baseline (speedup 1.0000x reference)
#include <cuda_runtime.h>
#include <math.h>

typedef unsigned long long ull;

#define BB 8
#define NN 64
#define HH 128
#define HEADS 4
#define HD 128
#define INNER 512
#define EE 8
#define NEdg 4032
#define LL 8
#define ROWS (BB*NN)   // 512
#define SPLITJ 8
#define JB (NN/SPLITJ) // 8
#define NB 256
#define NT 256

// ---------- persistent scratch ----------
__device__ float g_bufA[ROWS*HH];
__device__ float g_bufB[ROWS*HH];
__device__ float g_q[ROWS*INNER];
__device__ float g_k[ROWS*INNER];
__device__ float g_v[ROWS*INNER];
__device__ float g_P[ROWS*EE];
__device__ float g_D[ROWS*EE];
__device__ int   g_eid[NN*NN];
__device__ unsigned g_bar_cnt;
__device__ unsigned g_bar_gen;

// ---------- packed f32x2 helpers ----------
__device__ __forceinline__ ull fma2(ull a, ull b, ull c) {
    ull d; asm("fma.rn.f32x2 %0, %1, %2, %3;" : "=l"(d) : "l"(a), "l"(b), "l"(c)); return d;
}
__device__ __forceinline__ ull pk2(float x, float y) {
    ull r; unsigned a = __float_as_uint(x), b = __float_as_uint(y);
    asm("mov.b64 %0, {%1, %2};" : "=l"(r) : "r"(a), "r"(b)); return r;
}
__device__ __forceinline__ float f2sum(ull v) {
    unsigned a, b;
    asm("mov.b64 {%0, %1}, %2;" : "=r"(a), "=r"(b) : "l"(v));
    return __uint_as_float(a) + __uint_as_float(b);
}
__device__ __forceinline__ float f2lo(ull v) {
    unsigned a, b;
    asm("mov.b64 {%0, %1}, %2;" : "=r"(a), "=r"(b) : "l"(v));
    (void)b; return __uint_as_float(a);
}
__device__ __forceinline__ ull f4lo(float4 v) { return pk2(v.x, v.y); }
__device__ __forceinline__ ull f4hi(float4 v) { return pk2(v.z, v.w); }

// ---------- grid barrier ----------
__device__ __forceinline__ void grid_sync() {
    __syncthreads();
    if (threadIdx.x == 0) {
        __threadfence();
        unsigned gen = *(volatile unsigned*)&g_bar_gen;
        if (atomicAdd(&g_bar_cnt, 1u) == NB - 1) {
            *(volatile unsigned*)&g_bar_cnt = 0u;
            __threadfence();
            *(volatile unsigned*)&g_bar_gen = gen + 1u;
        } else {
            while (*(volatile unsigned*)&g_bar_gen == gen) { __nanosleep(32); }
        }
        __threadfence();
    }
    __syncthreads();
}

__global__ void __launch_bounds__(NT, 2) mega(
    const float* __restrict__ noise, const float* __restrict__ edge_attr,
    const int* __restrict__ eidx,
    const float* __restrict__ fc1_w, const float* __restrict__ fc1_b,
    const float* __restrict__ qw, const float* __restrict__ qb,
    const float* __restrict__ kw, const float* __restrict__ kb,
    const float* __restrict__ vw, const float* __restrict__ vb,
    const float* __restrict__ ew,
    const float* __restrict__ sw, const float* __restrict__ sb,
    const float* __restrict__ atom_w, const float* __restrict__ atom_b,
    const float* __restrict__ other_w, const float* __restrict__ other_b,
    const float* __restrict__ efw, const float* __restrict__ efb,
    float* __restrict__ out)
{
    __shared__ __align__(16) float smem[11392];   // 45.6KB static; 2 CTAs/SM
    const int t = threadIdx.x, blk = blockIdx.x;
    const int w = t >> 5, lane = t & 31;

    // ================= init =================
    if (blk < BB && t < HH) {
        float acc = fc1_b[t];
        #pragma unroll 4
        for (int i = 0; i < 128; i++) acc += noise[blk*128 + i] * fc1_w[i*HH + t];
        acc = fmaxf(acc, 0.f);
        for (int n = 0; n < NN; n++) g_bufA[(blk*NN + n)*HH + t] = acc;
    }
    { int e = blk*NT + t; if (e < NEdg) g_eid[eidx[e]*NN + eidx[NEdg + e]] = e; }
    grid_sync();

    float* xin = g_bufA;
    float* xout = g_bufB;

    for (int l = 0; l < LL; l++) {
        // ============ proj: 64x64 tiles; double-buffered; kp-pair-interleaved LDS.128 ============
        if (blk < 208) {
            // A: [2 buf][4 kp2][64 rows][2 ull]; B: [2 buf][4 kp2][64 cols][2 ull]
            ull* AsU = (ull*)smem;
            ull* BsU = ((ull*)smem) + 1024;
            int ct = blk % 26, rt = blk / 26;
            const float* W; const float* bias; int ld, coff; float* outp;
            if (ct < 8)       { W = qw + l*HH*INNER; bias = qb + l*INNER; ld = INNER; coff = ct*64;      outp = g_q; }
            else if (ct < 16) { W = kw + l*HH*INNER; bias = kb + l*INNER; ld = INNER; coff = (ct-8)*64;  outp = g_k; }
            else if (ct < 24) { W = vw + l*HH*INNER; bias = vb + l*INNER; ld = INNER; coff = (ct-16)*64; outp = g_v; }
            else              { W = sw + l*HH*HH;    bias = sb + l*HH;    ld = HH;    coff = (ct-24)*64; outp = xout; }
            const int tx = t & 15, ty = t >> 4;
            const int row_a = t & 63, kq = t >> 6;     // A loader: kp2 = kq
            const int col_b = t & 63, kpb = t >> 6;    // B loader: kp2 = kpb
            int r0 = rt*64;
            ull acc[4][4];
            #pragma unroll
            for (int r = 0; r < 4; r++)
                #pragma unroll
                for (int c = 0; c < 4; c++) acc[r][c] = 0ull;
            const float* arow_p = &xin[(r0+row_a)*HH + kq*4];
            const float* bcol_p = &W[coff + col_b];
            // prefetch k-tile 0
            float4 a4 = *(const float4*)arow_p;
            float bw0 = bcol_p[(4*kpb+0)*ld], bw1 = bcol_p[(4*kpb+1)*ld];
            float bw2 = bcol_p[(4*kpb+2)*ld], bw3 = bcol_p[(4*kpb+3)*ld];
            #pragma unroll
            for (int k0i = 0; k0i < 8; k0i++) {
                int bsel = (k0i & 1) << 9;
                AsU[bsel + kq*128 + row_a*2]     = pk2(fmaxf(a4.x,0.f), fmaxf(a4.y,0.f));
                AsU[bsel + kq*128 + row_a*2 + 1] = pk2(fmaxf(a4.z,0.f), fmaxf(a4.w,0.f));
                BsU[bsel + kpb*128 + col_b*2]     = pk2(bw0, bw1);
                BsU[bsel + kpb*128 + col_b*2 + 1] = pk2(bw2, bw3);
                __syncthreads();
                if (k0i < 7) {
                    int k0 = (k0i+1)*16;
                    a4 = *(const float4*)(arow_p + k0);
                    bw0 = bcol_p[(k0 + 4*kpb+0)*ld]; bw1 = bcol_p[(k0 + 4*kpb+1)*ld];
                    bw2 = bcol_p[(k0 + 4*kpb+2)*ld]; bw3 = bcol_p[(k0 + 4*kpb+3)*ld];
                }
                const ull* Ab = AsU + bsel;
                const ull* Bb = BsU + bsel;
                #pragma unroll
                for (int kp2 = 0; kp2 < 4; kp2++) {
                    ulonglong2 a2[4], b2[4];
                    #pragma unroll
                    for (int r = 0; r < 4; r++) a2[r] = *(const ulonglong2*)&Ab[kp2*128 + (ty + 16*r)*2];
                    #pragma unroll
                    for (int c = 0; c < 4; c++) b2[c] = *(const ulonglong2*)&Bb[kp2*128 + (tx + 16*c)*2];
                    #pragma unroll
                    for (int r = 0; r < 4; r++)
                        #pragma unroll
                        for (int c = 0; c < 4; c++) {
                            acc[r][c] = fma2(a2[r].x, b2[c].x, acc[r][c]);
                            acc[r][c] = fma2(a2[r].y, b2[c].y, acc[r][c]);
                        }
                }
            }
            #pragma unroll
            for (int r = 0; r < 4; r++)
                #pragma unroll
                for (int c = 0; c < 4; c++) {
                    int row = r0 + ty + 16*r, col = coff + tx + 16*c;
                    outp[row*ld + col] = f2sum(acc[r][c]) + bias[col];
                }
        }
        grid_sync();

        // ============ attn: quad-swizzled K, LDS.128 scores, dup-alpha aggV ============
        {
            float* sKV  = smem;            // [64][128]: K quad-swizzled, then V linear
            float* sQ   = smem + 8192;     // [8][128] (reused as aggV partial buffer)
            float* sEw  = smem + 9216;     // [8][128]
            ull*   sSd  = (ull*)(smem + 10240);   // [8][64] dup scores/alpha
            float* sQE  = smem + 11264;    // 64
            float* sAE  = smem + 11328;    // 64
            int jseg = blk & 7;
            int h = (blk >> 3) & 3;
            int b = blk >> 5;
            int jbase = jseg * JB;
            const float scale = 0.08838834764831845f;  // 1/sqrt(128)

            {   // eW
                int idx = t * 4;
                *(float4*)&sEw[idx] = *(const float4*)&ew[((size_t)l*EE + (idx >> 7))*INNER + h*HD + (idx & 127)];
            }
            {   // Q
                int idx = t * 4;
                *(float4*)&sQ[idx] = *(const float4*)&g_q[(b*NN + jbase + (idx >> 7))*INNER + h*HD + (idx & 127)];
            }
            // K quad-swizzled: quad qd of row r stored at sKV[r*128 + ((qd ^ (r&31))<<2)]
            for (int q4 = t; q4 < NN*32; q4 += NT) {
                int row = q4 >> 5, qd = q4 & 31;
                float4 v = *(const float4*)&g_k[(b*NN + row)*INNER + h*HD + qd*4];
                *(float4*)&sKV[row*128 + ((qd ^ (row & 31)) << 2)] = v;
            }
            __syncthreads();

            // qe[w][f] = q[row w]·eW[f]
            {
                const float* qrow = &sQ[w*HD];
                int f = lane & 7, seg = lane >> 3;
                const float* ewrow = &sEw[f*HD + seg*32];
                const float* qseg  = qrow + seg*32;
                float p = 0.f;
                #pragma unroll
                for (int i = 0; i < 32; i++) {
                    int d = (i + lane) & 31;
                    p += qseg[d] * ewrow[d];
                }
                p += __shfl_xor_sync(0xffffffffu, p, 8);
                p += __shfl_xor_sync(0xffffffffu, p, 16);
                if (lane < 8) sQE[w*8 + lane] = p;
            }
            __syncthreads();

            // scores: warp (jp, ih); lane -> i = ih*32+lane; rows 2jp, 2jp+1
            {
                int jp = w >> 1, ih = w & 1;
                int i = ih*32 + lane;
                int jl0 = jp*2, jl1 = jp*2 + 1;
                int j0 = jbase + jl0, j1 = jbase + jl1;
                // prefetch edge data (independent of score loop)
                const float* eabase = edge_attr + (size_t)b * NEdg * EE;
                int e0 = (i == j0) ? 0 : g_eid[i*NN + j0];
                int e1 = (i == j1) ? 0 : g_eid[i*NN + j1];
                float4 p0a = *(const float4*)&eabase[e0*EE];
                float4 p0b = *(const float4*)&eabase[e0*EE + 4];
                float4 p1a = *(const float4*)&eabase[e1*EE];
                float4 p1b = *(const float4*)&eabase[e1*EE + 4];
                const float* q0p = &sQ[jl0*HD];
                const float* q1p = &sQ[jl1*HD];
                const float* kr = &sKV[i*128];
                ull A0a = 0ull, A0b = 0ull, A1a = 0ull, A1b = 0ull;
                #pragma unroll 8
                for (int qd = 0; qd < 32; qd++) {
                    float4 kf = *(const float4*)&kr[(qd ^ lane) << 2];
                    float4 q0 = *(const float4*)&q0p[qd*4];
                    float4 q1 = *(const float4*)&q1p[qd*4];
                    A0a = fma2(f4lo(q0), f4lo(kf), A0a);
                    A0b = fma2(f4hi(q0), f4hi(kf), A0b);
                    A1a = fma2(f4lo(q1), f4lo(kf), A1a);
                    A1b = fma2(f4hi(q1), f4hi(kf), A1b);
                }
                float dot0 = f2sum(A0a) + f2sum(A0b);
                float dot1 = f2sum(A1a) + f2sum(A1b);
                const float* qe0 = &sQE[jl0*8];
                const float* qe1 = &sQE[jl1*8];
                float bs0 = p0a.x*qe0[0] + p0a.y*qe0[1] + p0a.z*qe0[2] + p0a.w*qe0[3]
                          + p0b.x*qe0[4] + p0b.y*qe0[5] + p0b.z*qe0[6] + p0b.w*qe0[7];
                float bs1 = p1a.x*qe1[0] + p1a.y*qe1[1] + p1a.z*qe1[2] + p1a.w*qe1[3]
                          + p1b.x*qe1[4] + p1b.y*qe1[5] + p1b.z*qe1[6] + p1b.w*qe1[7];
                float s0 = (i == j0) ? -1e30f : (dot0 + bs0) * scale;
                float s1 = (i == j1) ? -1e30f : (dot1 + bs1) * scale;
                sSd[jl0*64 + i] = pk2(s0, s0);
                sSd[jl1*64 + i] = pk2(s1, s1);
            }
            __syncthreads();

            // V restage (linear); readers wait at next sync
            for (int idx = t*4; idx < NN*HD; idx += NT*4)
                *(float4*)&sKV[idx] = *(const float4*)&g_v[(b*NN + (idx >> 7))*INNER + h*HD + (idx & 127)];

            // softmax + aggE: warp w owns row w
            {
                int jg = jbase + w;
                int i1 = lane, i2 = lane + 32;
                float s1 = f2lo(sSd[w*64 + i1]);
                float s2 = f2lo(sSd[w*64 + i2]);
                // prefetch edge data before the shuffle chain
                const float* eabase = edge_attr + (size_t)b * NEdg * EE;
                int e1 = (i1 == jg) ? 0 : g_eid[i1*NN + jg];
                int e2 = (i2 == jg) ? 0 : g_eid[i2*NN + jg];
                float4 ea1a = *(const float4*)&eabase[e1*EE];
                float4 ea1b = *(const float4*)&eabase[e1*EE + 4];
                float4 ea2a = *(const float4*)&eabase[e2*EE];
                float4 ea2b = *(const float4*)&eabase[e2*EE + 4];
                float m = fmaxf(s1, s2);
                #pragma unroll
                for (int o = 1; o < 32; o <<= 1) m = fmaxf(m, __shfl_xor_sync(0xffffffffu, m, o));
                float x1 = __expf(s1 - m), x2 = __expf(s2 - m);
                float sum = x1 + x2;
                #pragma unroll
                for (int o = 1; o < 32; o <<= 1) sum += __shfl_xor_sync(0xffffffffu, sum, o);
                float inv = 1.f / sum;
                float al1 = x1 * inv, al2 = x2 * inv;
                sSd[w*64 + i1] = pk2(al1, al1);
                sSd[w*64 + i2] = pk2(al2, al2);
                float ea1[8] = {ea1a.x, ea1a.y, ea1a.z, ea1a.w, ea1b.x, ea1b.y, ea1b.z, ea1b.w};
                float ea2[8] = {ea2a.x, ea2a.y, ea2a.z, ea2a.w, ea2b.x, ea2b.y, ea2b.z, ea2b.w};
                float ae[8];
                #pragma unroll
                for (int f = 0; f < 8; f++) {
                    float v = al1*ea1[f] + al2*ea2[f];
                    #pragma unroll
                    for (int o = 1; o < 32; o <<= 1) v += __shfl_xor_sync(0xffffffffu, v, o);
                    ae[f] = v;
                }
                if (lane == 0) {
                    #pragma unroll
                    for (int f = 0; f < 8; f++) sAE[w*8 + f] = ae[f];
                }
            }
            __syncthreads();

            // aggV: warp (jp, iseg); rows 2jp, 2jp+1; lane owns d-quad d0 = lane*4
            {
                int jp = w >> 1, iseg = w & 1;
                int jl0 = jp*2, jl1 = jl0 + 1;
                int d0 = lane * 4;
                ull P0a = 0ull, P0b = 0ull, P1a = 0ull, P1b = 0ull;
                int ibase = iseg * 32;
                #pragma unroll 4
                for (int ii = 0; ii < 32; ii++) {
                    int i = ibase + ii;
                    ull a0 = sSd[jl0*64 + i];        // dup alpha, LDS.64 broadcast
                    ull a1 = sSd[jl1*64 + i];
                    float4 v = *(const float4*)&sKV[i*HD + d0];
                    ull vlo = f4lo(v), vhi = f4hi(v);
                    P0a = fma2(a0, vlo, P0a); P0b = fma2(a0, vhi, P0b);
                    P1a = fma2(a1, vlo, P1a); P1b = fma2(a1, vhi, P1b);
                }
                if (iseg == 1) {
                    // write partials into sQ (Q is dead now)
                    *(float2*)&sQ[jl0*128 + d0]     = make_float2(f2lo(P0a), __uint_as_float((unsigned)(P0a>>32)));
                    *(ull*)&sQ[jl0*128 + d0]     = P0a;
                    *(ull*)&sQ[jl0*128 + d0 + 2] = P0b;
                    *(ull*)&sQ[jl1*128 + d0]     = P1a;
                    *(ull*)&sQ[jl1*128 + d0 + 2] = P1b;
                }
                __syncthreads();
                if (iseg == 0) {
                    // add partner partials + eW term, emit atomics
                    ull Q0a = *(ull*)&sQ[jl0*128 + d0];
                    ull Q0b = *(ull*)&sQ[jl0*128 + d0 + 2];
                    ull Q1a = *(ull*)&sQ[jl1*128 + d0];
                    ull Q1b = *(ull*)&sQ[jl1*128 + d0 + 2];
                    float r00 = f2lo(P0a) + f2lo(Q0a);
                    float r01 = __uint_as_float((unsigned)(P0a>>32)) + __uint_as_float((unsigned)(Q0a>>32));
                    float r02 = f2lo(P0b) + f2lo(Q0b);
                    float r03 = __uint_as_float((unsigned)(P0b>>32)) + __uint_as_float((unsigned)(Q0b>>32));
                    float r10 = f2lo(P1a) + f2lo(Q1a);
                    float r11 = __uint_as_float((unsigned)(P1a>>32)) + __uint_as_float((unsigned)(Q1a>>32));
                    float r12 = f2lo(P1b) + f2lo(Q1b);
                    float r13 = __uint_as_float((unsigned)(P1b>>32)) + __uint_as_float((unsigned)(Q1b>>32));
                    #pragma unroll
                    for (int f = 0; f < 8; f++) {
                        float ae0 = sAE[jl0*8 + f], ae1 = sAE[jl1*8 + f];
                        float4 wv = *(const float4*)&sEw[f*HD + d0];
                        r00 += ae0*wv.x; r01 += ae0*wv.y; r02 += ae0*wv.z; r03 += ae0*wv.w;
                        r10 += ae1*wv.x; r11 += ae1*wv.y; r12 += ae1*wv.z; r13 += ae1*wv.w;
                    }
                    float* d0p = &xout[(b*NN + jbase + jl0)*HH + d0];
                    float* d1p = &xout[(b*NN + jbase + jl1)*HH + d0];
                    atomicAdd(d0p+0, 0.25f*r00); atomicAdd(d0p+1, 0.25f*r01);
                    atomicAdd(d0p+2, 0.25f*r02); atomicAdd(d0p+3, 0.25f*r03);
                    atomicAdd(d1p+0, 0.25f*r10); atomicAdd(d1p+1, 0.25f*r11);
                    atomicAdd(d1p+2, 0.25f*r12); atomicAdd(d1p+3, 0.25f*r13);
                }
            }
        }
        grid_sync();
        float* tmp = xin; xin = xout; xout = tmp;
    }

    // ================= node head + P/D (2 nodes per block) =================
    {
        float* xr   = smem;         // [2][128]
        float* outs = smem + 256;   // [2][40]
        float* red  = smem + 336;   // [2][2]
        int sub = t >> 7, tl = t & 127;
        int node = blk*2 + sub;
        xr[sub*128 + tl] = fmaxf(xin[node*128 + tl], 0.f);
        __syncthreads();
        if (tl < 40) {
            const float* xp = &xr[sub*128];
            float acc;
            if (tl < 9)       { acc = atom_b[tl];  for (int d = 0; d < HH; d++) acc += xp[d]*atom_w[d*9+tl]; }
            else if (tl < 24) { int c = tl-9;  acc = other_b[c]; for (int d = 0; d < HH; d++) acc += xp[d]*other_w[d*15+c]; }
            else if (tl < 32) { int f = tl-24; acc = 0.f; for (int d = 0; d < HH; d++) acc += xp[d]*efw[d*EE+f]; }
            else              { int f = tl-32; acc = 0.f; for (int d = 0; d < HH; d++) acc += xp[d]*efw[(128+d)*EE+f]; }
            outs[sub*40 + tl] = acc;
        }
        __syncthreads();
        if (tl == 0) {
            float m = -1e30f;
            for (int a = 0; a < 9; a++) m = fmaxf(m, outs[sub*40+a]);
            float s = 0.f;
            for (int a = 0; a < 9; a++) s += __expf(outs[sub*40+a]-m);
            red[sub*2] = m; red[sub*2+1] = s;
        }
        __syncthreads();
        if (tl < 9) {
            float p = __expf(outs[sub*40+tl]-red[sub*2]) / red[sub*2+1];
            out[node*24 + tl] = 1.f/(1.f + __expf(-p));
        } else if (tl < 24) {
            float o = 1.f/(1.f + __expf(-outs[sub*40+tl]));
            out[node*24 + tl] = 1.f/(1.f + __expf(-o));
        } else if (tl < 32) {
            g_P[node*EE + (tl-24)] = outs[sub*40+tl];
        } else if (tl < 40) {
            g_D[node*EE + (tl-32)] = outs[sub*40+tl];
        }
    }
    grid_sync();

    // ================= edge head =================
    if (t < 126) {
        int eg = blk*126 + t;     // 256*126 = 32256
        int b = eg / NEdg, e = eg % NEdg;
        int s = eidx[e], d = eidx[NEdg + e];
        const float* P = &g_P[(b*NN + s)*EE];
        const float* D = &g_D[(b*NN + d)*EE];
        float* o = out + (size_t)ROWS*24 + (size_t)eg*EE;
        #pragma unroll
        for (int f = 0; f < EE; f++) {
            float v = P[f] + D[f] + efb[f];
            o[f] = 1.f/(1.f + __expf(-v));
        }
    }
}

extern "C" void kernel_launch(void* const* d_in, const int* in_sizes, int n_in,
                              void* d_out, int out_size) {
    const float* noise     = (const float*)d_in[0];
    const float* edge_attr = (const float*)d_in[1];
    const int*   edge_index= (const int*)  d_in[2];
    const float* fc1_w     = (const float*)d_in[3];
    const float* fc1_b     = (const float*)d_in[4];
    const float* q_w       = (const float*)d_in[5];
    const float* q_b       = (const float*)d_in[6];
    const float* k_w       = (const float*)d_in[7];
    const float* k_b       = (const float*)d_in[8];
    const float* v_w       = (const float*)d_in[9];
    const float* v_b       = (const float*)d_in[10];
    const float* e_w       = (const float*)d_in[11];
    const float* skip_w    = (const float*)d_in[12];
    const float* skip_b    = (const float*)d_in[13];
    const float* atom_w    = (const float*)d_in[14];
    const float* atom_b    = (const float*)d_in[15];
    const float* other_w   = (const float*)d_in[16];
    const float* other_b   = (const float*)d_in[17];
    const float* efw       = (const float*)d_in[18];
    const float* efb       = (const float*)d_in[19];
    float* out = (float*)d_out;

    mega<<<NB, NT>>>(noise, edge_attr, edge_index, fc1_w, fc1_b,
                     q_w, q_b, k_w, k_b, v_w, v_b, e_w, skip_w, skip_b,
                     atom_w, atom_b, other_w, other_b, efw, efb, out);
}

// round 8
// speedup vs baseline: 1.0071x; 1.0071x over previous
#include <cuda_runtime.h>
#include <math.h>

typedef unsigned long long ull;

#define BB 8
#define NN 64
#define HH 128
#define HEADS 4
#define HD 128
#define INNER 512
#define EE 8
#define NEdg 4032
#define LL 8
#define ROWS (BB*NN)   // 512
#define SPLITJ 8
#define JB (NN/SPLITJ) // 8
#define NB 256
#define NT 256

// ---------- persistent scratch ----------
__device__ float g_bufA[ROWS*HH];
__device__ float g_bufB[ROWS*HH];
__device__ float g_q[ROWS*INNER];
__device__ float g_k[ROWS*INNER];
__device__ float g_v[ROWS*INNER];
__device__ float g_P[ROWS*EE];
__device__ float g_D[ROWS*EE];
__device__ int   g_eid[NN*NN];
__device__ unsigned g_bar_cnt;
__device__ unsigned g_bar_gen;
// dataflow sync state (reset each launch before the init barrier)
__device__ unsigned g_tflag[BB*26];    // proj tile (rt, ct) -> layer stamp l+1
__device__ unsigned g_attn_done[BB];   // attn CTAs completed per graph (cumulative)
__device__ unsigned g_node_done;       // node-head CTAs completed

// ---------- packed f32x2 helpers ----------
__device__ __forceinline__ ull fma2(ull a, ull b, ull c) {
    ull d; asm("fma.rn.f32x2 %0, %1, %2, %3;" : "=l"(d) : "l"(a), "l"(b), "l"(c)); return d;
}
__device__ __forceinline__ ull pk2(float x, float y) {
    ull r; unsigned a = __float_as_uint(x), b = __float_as_uint(y);
    asm("mov.b64 %0, {%1, %2};" : "=l"(r) : "r"(a), "r"(b)); return r;
}
__device__ __forceinline__ float f2sum(ull v) {
    unsigned a, b;
    asm("mov.b64 {%0, %1}, %2;" : "=r"(a), "=r"(b) : "l"(v));
    return __uint_as_float(a) + __uint_as_float(b);
}

// ---------- single init-time grid barrier ----------
__device__ __forceinline__ void grid_sync() {
    __syncthreads();
    if (threadIdx.x == 0) {
        __threadfence();
        unsigned gen = *(volatile unsigned*)&g_bar_gen;
        if (atomicAdd(&g_bar_cnt, 1u) == NB - 1) {
            *(volatile unsigned*)&g_bar_cnt = 0u;
            __threadfence();
            *(volatile unsigned*)&g_bar_gen = gen + 1u;
        } else {
            while (*(volatile unsigned*)&g_bar_gen == gen) { }
        }
        __threadfence();
    }
    __syncthreads();
}

__global__ void __launch_bounds__(NT, 2) mega(
    const float* __restrict__ noise, const float* __restrict__ edge_attr,
    const int* __restrict__ eidx,
    const float* __restrict__ fc1_w, const float* __restrict__ fc1_b,
    const float* __restrict__ qw, const float* __restrict__ qb,
    const float* __restrict__ kw, const float* __restrict__ kb,
    const float* __restrict__ vw, const float* __restrict__ vb,
    const float* __restrict__ ew,
    const float* __restrict__ sw, const float* __restrict__ sb,
    const float* __restrict__ atom_w, const float* __restrict__ atom_b,
    const float* __restrict__ other_w, const float* __restrict__ other_b,
    const float* __restrict__ efw, const float* __restrict__ efb,
    float* __restrict__ out)
{
    __shared__ __align__(16) float smem[10912];
    const int t = threadIdx.x, blk = blockIdx.x;
    const int w = t >> 5, lane = t & 31;

    // ================= init + sync-state reset =================
    if (blk < BB && t < HH) {
        float acc = fc1_b[t];
        #pragma unroll 4
        for (int i = 0; i < 128; i++) acc += noise[blk*128 + i] * fc1_w[i*HH + t];
        acc = fmaxf(acc, 0.f);
        for (int n = 0; n < NN; n++) g_bufA[(blk*NN + n)*HH + t] = acc;
        __threadfence();
    }
    { int e = blk*NT + t; if (e < NEdg) { g_eid[eidx[e]*NN + eidx[NEdg + e]] = e; __threadfence(); } }
    if (blk == 8) {
        if (t < BB*26) g_tflag[t] = 0u;
        else if (t < BB*26 + BB) g_attn_done[t - BB*26] = 0u;
        else if (t == BB*26 + BB) g_node_done = 0u;
        __threadfence();
    }
    grid_sync();

    float* xin = g_bufA;
    float* xout = g_bufB;

    for (int l = 0; l < LL; l++) {
        // ============ proj: 64x64 tiles; gated by attn_done[rt] of previous layer ============
        if (blk < 208) {
            int ct = blk % 26, rt = blk / 26;
            if (t == 0) {
                if (l) { while (atomicAdd(&g_attn_done[rt], 0u) < (unsigned)(32*l)) { } }
                __threadfence();
            }
            __syncthreads();

            ull* AsU = (ull*)smem;           // [2][8 kp][64 rows]
            ull* BsU = ((ull*)smem) + 1024;  // [2][8 kp][64 cols]
            const float* W; const float* bias; int ld, coff; float* outp;
            if (ct < 8)       { W = qw + l*HH*INNER; bias = qb + l*INNER; ld = INNER; coff = ct*64;      outp = g_q; }
            else if (ct < 16) { W = kw + l*HH*INNER; bias = kb + l*INNER; ld = INNER; coff = (ct-8)*64;  outp = g_k; }
            else if (ct < 24) { W = vw + l*HH*INNER; bias = vb + l*INNER; ld = INNER; coff = (ct-16)*64; outp = g_v; }
            else              { W = sw + l*HH*HH;    bias = sb + l*HH;    ld = HH;    coff = (ct-24)*64; outp = xout; }
            const int tx = t & 15, ty = t >> 4;
            const int row_a = t & 63, kq = t >> 6;
            const int col_b = t & 63, kpb = t >> 6;
            int r0 = rt*64;
            ull acc[4][4];
            #pragma unroll
            for (int r = 0; r < 4; r++)
                #pragma unroll
                for (int c = 0; c < 4; c++) acc[r][c] = 0ull;
            const float* arow_p = &xin[(r0+row_a)*HH + kq*4];
            const float* bcol_p = &W[coff + col_b];
            float4 a4 = *(const float4*)arow_p;
            float bw0 = bcol_p[(2*kpb)*ld],     bw1 = bcol_p[(2*kpb+1)*ld];
            float bw2 = bcol_p[(2*kpb+8)*ld],   bw3 = bcol_p[(2*kpb+9)*ld];
            #pragma unroll
            for (int k0i = 0; k0i < 8; k0i++) {
                int bsel = (k0i & 1) << 9;
                AsU[bsel + (2*kq)*64 + row_a]   = pk2(fmaxf(a4.x,0.f), fmaxf(a4.y,0.f));
                AsU[bsel + (2*kq+1)*64 + row_a] = pk2(fmaxf(a4.z,0.f), fmaxf(a4.w,0.f));
                BsU[bsel + kpb*64 + col_b]      = pk2(bw0, bw1);
                BsU[bsel + (kpb+4)*64 + col_b]  = pk2(bw2, bw3);
                __syncthreads();
                if (k0i < 7) {
                    int k0 = (k0i+1)*16;
                    a4 = *(const float4*)(arow_p + k0);
                    bw0 = bcol_p[(k0 + 2*kpb)*ld];   bw1 = bcol_p[(k0 + 2*kpb+1)*ld];
                    bw2 = bcol_p[(k0 + 2*kpb+8)*ld]; bw3 = bcol_p[(k0 + 2*kpb+9)*ld];
                }
                const ull* Ab = AsU + bsel;
                const ull* Bb = BsU + bsel;
                #pragma unroll
                for (int kp = 0; kp < 8; kp++) {
                    ull a2[4], b2[4];
                    #pragma unroll
                    for (int r = 0; r < 4; r++) a2[r] = Ab[kp*64 + ty + 16*r];
                    #pragma unroll
                    for (int c = 0; c < 4; c++) b2[c] = Bb[kp*64 + tx + 16*c];
                    #pragma unroll
                    for (int r = 0; r < 4; r++)
                        #pragma unroll
                        for (int c = 0; c < 4; c++) acc[r][c] = fma2(a2[r], b2[c], acc[r][c]);
                }
            }
            #pragma unroll
            for (int r = 0; r < 4; r++)
                #pragma unroll
                for (int c = 0; c < 4; c++) {
                    int row = r0 + ty + 16*r, col = coff + tx + 16*c;
                    outp[row*ld + col] = f2sum(acc[r][c]) + bias[col];
                }
            // release: tile complete
            __threadfence();
            __syncthreads();
            if (t == 0) atomicExch(&g_tflag[rt*26 + ct], (unsigned)(l + 1));
        }

        // ============ attn: gated by its 8 tile flags ============
        {
            int jseg = blk & 7;
            int h = (blk >> 3) & 3;
            int b = blk >> 5;
            int jbase = jseg * JB;
            const float scale = 0.08838834764831845f;  // 1/sqrt(128)

            if (t < 8) {
                int ctf = (t < 6) ? ((t >> 1) * 8 + 2*h + (t & 1)) : (24 + (t & 1));
                unsigned tgt = (unsigned)(l + 1);
                while (atomicAdd(&g_tflag[b*26 + ctf], 0u) < tgt) { }
            }
            if (t == 0) __threadfence();
            __syncthreads();

            float* sKV = smem;            // [64][128]: K swizzled, then V linear
            float* sQ  = smem + 8192;     // [8][128]
            float* sEw = smem + 9216;     // [8][128]
            float (*sS)[68] = (float(*)[68])(smem + 10240);
            float* sQE = smem + 10784;
            float* sAE = smem + 10848;

            {   // eW
                int idx = t * 4;
                *(float4*)&sEw[idx] = *(const float4*)&ew[((size_t)l*EE + (idx >> 7))*INNER + h*HD + (idx & 127)];
            }
            {   // Q
                int idx = t * 4;
                *(float4*)&sQ[idx] = *(const float4*)&g_q[(b*NN + jbase + (idx >> 7))*INNER + h*HD + (idx & 127)];
            }
            // K pair-swizzled
            for (int q4 = t; q4 < NN*32; q4 += NT) {
                int row = q4 >> 5, dq = (q4 & 31) << 2;
                float4 v = *(const float4*)&g_k[(b*NN + row)*INNER + h*HD + dq];
                int rx = row & 31;
                float* base = &sKV[row*128];
                float2 lo = {v.x, v.y}, hi = {v.z, v.w};
                *(float2*)&base[((dq >> 1) ^ rx) << 1] = lo;
                *(float2*)&base[(((dq >> 1) + 1) ^ rx) << 1] = hi;
            }
            __syncthreads();

            // qe[w][f] = q[row w]·eW[f]
            {
                const float* qrow = &sQ[w*HD];
                int f = lane & 7, seg = lane >> 3;
                const float* ewrow = &sEw[f*HD + seg*32];
                const float* qseg  = qrow + seg*32;
                float p = 0.f;
                #pragma unroll
                for (int i = 0; i < 32; i++) {
                    int d = (i + lane) & 31;
                    p += qseg[d] * ewrow[d];
                }
                p += __shfl_xor_sync(0xffffffffu, p, 8);
                p += __shfl_xor_sync(0xffffffffu, p, 16);
                if (lane < 8) sQE[w*8 + lane] = p;
            }
            __syncthreads();

            // scores: warp (jp, ih); lane -> src i = ih*32+lane; rows 2jp, 2jp+1
            {
                int jp = w >> 1, ih = w & 1;
                int i = ih*32 + lane;
                int jl0 = jp*2, jl1 = jp*2 + 1;
                int j0 = jbase + jl0, j1 = jbase + jl1;
                const ull* q0p = (const ull*)&sQ[jl0*HD];
                const ull* q1p = (const ull*)&sQ[jl1*HD];
                const float* kr = &sKV[i*128];
                ull A0 = 0ull, A1 = 0ull;
                #pragma unroll 8
                for (int d2 = 0; d2 < 64; d2++) {
                    ull kv = *(const ull*)&kr[(d2 ^ lane) << 1];
                    A0 = fma2(q0p[d2], kv, A0);
                    A1 = fma2(q1p[d2], kv, A1);
                }
                float dot0 = f2sum(A0), dot1 = f2sum(A1);
                const float* eabase = edge_attr + (size_t)b * NEdg * EE;
                int e0 = (i == j0) ? 0 : g_eid[i*NN + j0];
                int e1 = (i == j1) ? 0 : g_eid[i*NN + j1];
                float4 p0a = *(const float4*)&eabase[e0*EE];
                float4 p0b = *(const float4*)&eabase[e0*EE + 4];
                float4 p1a = *(const float4*)&eabase[e1*EE];
                float4 p1b = *(const float4*)&eabase[e1*EE + 4];
                const float* qe0 = &sQE[jl0*8];
                const float* qe1 = &sQE[jl1*8];
                float bs0 = p0a.x*qe0[0] + p0a.y*qe0[1] + p0a.z*qe0[2] + p0a.w*qe0[3]
                          + p0b.x*qe0[4] + p0b.y*qe0[5] + p0b.z*qe0[6] + p0b.w*qe0[7];
                float bs1 = p1a.x*qe1[0] + p1a.y*qe1[1] + p1a.z*qe1[2] + p1a.w*qe1[3]
                          + p1b.x*qe1[4] + p1b.y*qe1[5] + p1b.z*qe1[6] + p1b.w*qe1[7];
                sS[jl0][i] = (i == j0) ? -1e30f : (dot0 + bs0) * scale;
                sS[jl1][i] = (i == j1) ? -1e30f : (dot1 + bs1) * scale;
            }
            __syncthreads();

            // V restage (issue early; readers wait at next sync)
            for (int idx = t*4; idx < NN*HD; idx += NT*4)
                *(float4*)&sKV[idx] = *(const float4*)&g_v[(b*NN + (idx >> 7))*INNER + h*HD + (idx & 127)];

            // softmax + aggE: warp w owns row w
            {
                int jg = jbase + w;
                float s1 = sS[w][lane], s2 = sS[w][lane + 32];
                float m = fmaxf(s1, s2);
                #pragma unroll
                for (int o = 1; o < 32; o <<= 1) m = fmaxf(m, __shfl_xor_sync(0xffffffffu, m, o));
                float x1 = __expf(s1 - m), x2 = __expf(s2 - m);
                float sum = x1 + x2;
                #pragma unroll
                for (int o = 1; o < 32; o <<= 1) sum += __shfl_xor_sync(0xffffffffu, sum, o);
                float inv = 1.f / sum;
                float al1 = x1 * inv, al2 = x2 * inv;
                sS[w][lane] = al1;
                sS[w][lane + 32] = al2;
                int i1 = lane, i2 = lane + 32;
                const float* eabase = edge_attr + (size_t)b * NEdg * EE;
                int e1 = (i1 == jg) ? 0 : g_eid[i1*NN + jg];
                int e2 = (i2 == jg) ? 0 : g_eid[i2*NN + jg];
                float4 ea1a = *(const float4*)&eabase[e1*EE];
                float4 ea1b = *(const float4*)&eabase[e1*EE + 4];
                float4 ea2a = *(const float4*)&eabase[e2*EE];
                float4 ea2b = *(const float4*)&eabase[e2*EE + 4];
                float ea1[8] = {ea1a.x, ea1a.y, ea1a.z, ea1a.w, ea1b.x, ea1b.y, ea1b.z, ea1b.w};
                float ea2[8] = {ea2a.x, ea2a.y, ea2a.z, ea2a.w, ea2b.x, ea2b.y, ea2b.z, ea2b.w};
                float ae[8];
                #pragma unroll
                for (int f = 0; f < 8; f++) {
                    float v = al1*ea1[f] + al2*ea2[f];
                    #pragma unroll
                    for (int o = 1; o < 32; o <<= 1) v += __shfl_xor_sync(0xffffffffu, v, o);
                    ae[f] = v;
                }
                if (lane == 0) {
                    #pragma unroll
                    for (int f = 0; f < 8; f++) sAE[w*8 + f] = ae[f];
                }
            }
            __syncthreads();

            // aggV: warp (jp2, dh); rows 2jp2, 2jp2+1; lane d = dh*64 + lane*2
            {
                int jp2 = w >> 1, dh = w & 1;
                int jl0 = jp2*2, jl1 = jl0 + 1;
                int d0 = dh*64 + lane*2;
                float a00 = 0.f, a01 = 0.f, a10 = 0.f, a11 = 0.f;
                #pragma unroll 4
                for (int i = 0; i < NN; i++) {
                    float al0 = sS[jl0][i], al1 = sS[jl1][i];
                    float2 v = *(const float2*)&sKV[i*HD + d0];
                    a00 += al0*v.x; a01 += al0*v.y;
                    a10 += al1*v.x; a11 += al1*v.y;
                }
                #pragma unroll
                for (int f = 0; f < 8; f++) {
                    float ae0 = sAE[jl0*8 + f], ae1 = sAE[jl1*8 + f];
                    float2 wv = *(const float2*)&sEw[f*HD + d0];
                    a00 += ae0*wv.x; a01 += ae0*wv.y;
                    a10 += ae1*wv.x; a11 += ae1*wv.y;
                }
                float* d0p = &xout[(b*NN + jbase + jl0)*HH + d0];
                float* d1p = &xout[(b*NN + jbase + jl1)*HH + d0];
                atomicAdd(d0p+0, 0.25f*a00);
                atomicAdd(d0p+1, 0.25f*a01);
                atomicAdd(d1p+0, 0.25f*a10);
                atomicAdd(d1p+1, 0.25f*a11);
            }
            // release: this (b,h,jseg) fully accumulated
            __threadfence();
            __syncthreads();
            if (t == 0) atomicAdd(&g_attn_done[b], 1u);
        }
        float* tmp = xin; xin = xout; xout = tmp;
    }

    // ================= node head + P/D (2 nodes per block); gated on graph complete =================
    {
        if (t == 0) {
            while (atomicAdd(&g_attn_done[blk >> 5], 0u) < (unsigned)(32*LL)) { }
            __threadfence();
        }
        __syncthreads();

        float* xr   = smem;
        float* outs = smem + 256;
        float* red  = smem + 336;
        int sub = t >> 7, tl = t & 127;
        int node = blk*2 + sub;
        xr[sub*128 + tl] = fmaxf(xin[node*128 + tl], 0.f);
        __syncthreads();
        if (tl < 40) {
            const float* xp = &xr[sub*128];
            float acc;
            if (tl < 9)       { acc = atom_b[tl];  for (int d = 0; d < HH; d++) acc += xp[d]*atom_w[d*9+tl]; }
            else if (tl < 24) { int c = tl-9;  acc = other_b[c]; for (int d = 0; d < HH; d++) acc += xp[d]*other_w[d*15+c]; }
            else if (tl < 32) { int f = tl-24; acc = 0.f; for (int d = 0; d < HH; d++) acc += xp[d]*efw[d*EE+f]; }
            else              { int f = tl-32; acc = 0.f; for (int d = 0; d < HH; d++) acc += xp[d]*efw[(128+d)*EE+f]; }
            outs[sub*40 + tl] = acc;
        }
        __syncthreads();
        if (tl == 0) {
            float m = -1e30f;
            for (int a = 0; a < 9; a++) m = fmaxf(m, outs[sub*40+a]);
            float s = 0.f;
            for (int a = 0; a < 9; a++) s += __expf(outs[sub*40+a]-m);
            red[sub*2] = m; red[sub*2+1] = s;
        }
        __syncthreads();
        if (tl < 9) {
            float p = __expf(outs[sub*40+tl]-red[sub*2]) / red[sub*2+1];
            out[node*24 + tl] = 1.f/(1.f + __expf(-p));
        } else if (tl < 24) {
            float o = 1.f/(1.f + __expf(-outs[sub*40+tl]));
            out[node*24 + tl] = 1.f/(1.f + __expf(-o));
        } else if (tl < 32) {
            g_P[node*EE + (tl-24)] = outs[sub*40+tl];
        } else if (tl < 40) {
            g_D[node*EE + (tl-32)] = outs[sub*40+tl];
        }
        __threadfence();
        __syncthreads();
        if (t == 0) atomicAdd(&g_node_done, 1u);
    }

    // ================= edge head: gated on all node heads =================
    {
        if (t == 0) {
            while (atomicAdd(&g_node_done, 0u) < 256u) { }
            __threadfence();
        }
        __syncthreads();
        if (t < 126) {
            int eg = blk*126 + t;     // 256*126 = 32256
            int b = eg / NEdg, e = eg % NEdg;
            int s = eidx[e], d = eidx[NEdg + e];
            const float* P = &g_P[(b*NN + s)*EE];
            const float* D = &g_D[(b*NN + d)*EE];
            float* o = out + (size_t)ROWS*24 + (size_t)eg*EE;
            #pragma unroll
            for (int f = 0; f < EE; f++) {
                float v = P[f] + D[f] + efb[f];
                o[f] = 1.f/(1.f + __expf(-v));
            }
        }
    }
}

extern "C" void kernel_launch(void* const* d_in, const int* in_sizes, int n_in,
                              void* d_out, int out_size) {
    const float* noise     = (const float*)d_in[0];
    const float* edge_attr = (const float*)d_in[1];
    const int*   edge_index= (const int*)  d_in[2];
    const float* fc1_w     = (const float*)d_in[3];
    const float* fc1_b     = (const float*)d_in[4];
    const float* q_w       = (const float*)d_in[5];
    const float* q_b       = (const float*)d_in[6];
    const float* k_w       = (const float*)d_in[7];
    const float* k_b       = (const float*)d_in[8];
    const float* v_w       = (const float*)d_in[9];
    const float* v_b       = (const float*)d_in[10];
    const float* e_w       = (const float*)d_in[11];
    const float* skip_w    = (const float*)d_in[12];
    const float* skip_b    = (const float*)d_in[13];
    const float* atom_w    = (const float*)d_in[14];
    const float* atom_b    = (const float*)d_in[15];
    const float* other_w   = (const float*)d_in[16];
    const float* other_b   = (const float*)d_in[17];
    const float* efw       = (const float*)d_in[18];
    const float* efb       = (const float*)d_in[19];
    float* out = (float*)d_out;

    mega<<<NB, NT>>>(noise, edge_attr, edge_index, fc1_w, fc1_b,
                     q_w, q_b, k_w, k_b, v_w, v_b, e_w, skip_w, skip_b,
                     atom_w, atom_b, other_w, other_b, efw, efb, out);
}